// round 3
// baseline (speedup 1.0000x reference)
#include <cuda_runtime.h>

// FD_discretizer: fused, y-coarsened (KY=4) register-rolling stencil.
// 1024x1024 grid, extended 1026x1026. Index arrays closed-form in (i,j).
// Identities: obm == ebm[interior]; interior ext == raw uvp.

#define NXg 1024
#define NYg 1024
#define EX  1026
#define EY  1026
#define NN  (NXg*NYg)

#define PRESS_E (513*EX + 513)

#define TXg 32
#define TYg 4
#define KY  4
#define NTHR (TXg*TYg)          // 128
#define OUT_H (TYg*KY)          // 16
#define EXT_W (TXg + 2)         // 34
#define EXT_H (OUT_H + 2)       // 18
#define TILE  (EXT_W * EXT_H)   // 612

__device__ __forceinline__ int clampi(int x, int lo, int hi) {
    return x < lo ? lo : (x > hi ? hi : x);
}
__device__ __forceinline__ int eidx(int je, int ie) {
    return clampi(je - 1, 0, NYg - 1) * NXg + clampi(ie - 1, 0, NXg - 1);
}

struct F3 { float x, y, z; };

__device__ __forceinline__ void dummy_uv(const float* __restrict__ uvp,
                                         const float* __restrict__ ny,
                                         int m, float& du, float& dv) {
    int io = m % NXg;
    int jo = m / NXg;
    bool bc = (io == 0) || (io != NXg - 1 && (jo == 0 || jo == NYg - 1));
    if (bc) { du = ny[3*m]; dv = ny[3*m+1]; }
    else    { du = uvp[3*m]; dv = uvp[3*m+1]; }
}
__device__ __forceinline__ float dummy_p(const float* __restrict__ uvp, int m) {
    int io = m % NXg;
    return (io == NXg - 1) ? 0.0f : uvp[3*m+2];
}

__device__ __forceinline__ F3 ext_val(const float* __restrict__ uvp,
                                      const float* __restrict__ ny,
                                      int je, int ie) {
    F3 r;
    bool jin = (je >= 1) & (je <= EY - 2);
    if (ie == 0 && jin) {               // left ghost: INFLOW -> pmask
        int m1 = eidx(je, 1), m2 = eidx(je, 2);
        float du, dv; dummy_uv(uvp, ny, m1, du, dv);
        r.x = 2.0f*du - uvp[3*m2];
        r.y = 2.0f*dv - uvp[3*m2+1];
        r.z = uvp[3*m2+2];
    } else if (ie == EX - 1 && jin) {   // right ghost: OUTFLOW -> uvmask
        int m1 = eidx(je, EX - 2), m2 = eidx(je, EX - 3);
        float dp = dummy_p(uvp, m1);
        r.x = uvp[3*m2];
        r.y = uvp[3*m2+1];
        r.z = 2.0f*dp - uvp[3*m2+2];
    } else if (je == 0 && ie >= 1 && ie <= EX - 2) {   // bottom ghost: WALL
        int m1 = eidx(1, ie), m2 = eidx(2, ie);
        float du, dv; dummy_uv(uvp, ny, m1, du, dv);
        r.x = 2.0f*du - uvp[3*m2];
        r.y = 2.0f*dv - uvp[3*m2+1];
        r.z = uvp[3*m2+2];
    } else if (je == EY - 1 && ie >= 1 && ie <= EX - 2) {  // top ghost: WALL
        int m1 = eidx(EY - 2, ie), m2 = eidx(EY - 3, ie);
        float du, dv; dummy_uv(uvp, ny, m1, du, dv);
        r.x = 2.0f*du - uvp[3*m2];
        r.y = 2.0f*dv - uvp[3*m2+1];
        r.z = uvp[3*m2+2];
    } else {
        int m = eidx(je, ie);
        r.x = uvp[3*m]; r.y = uvp[3*m+1]; r.z = uvp[3*m+2];
    }
    return r;
}

// Rolling row window: everything read with a y-dependence.
struct Row {
    float eu[3], ev[3], ep[3];   // cols c-1, c, c+1
    float eou, eov;              // col c
    float V, Vo, a22, pex, pey;  // col c
};

__global__ void __launch_bounds__(NTHR, 5)
fused_kernel(const float* __restrict__ ouv,
             const float* __restrict__ ouv_old,
             const float* __restrict__ ny,
             const float* __restrict__ ebm,
             const float* __restrict__ dtg,
             const float* __restrict__ theta,
             const float* __restrict__ relp,
             float* __restrict__ out) {
    __shared__ float s_eu [TILE];
    __shared__ float s_ev [TILE];
    __shared__ float s_ep [TILE];
    __shared__ float s_eou[TILE];
    __shared__ float s_eov[TILE];
    __shared__ float s_U  [TILE];
    __shared__ float s_V  [TILE];
    __shared__ float s_Uo [TILE];
    __shared__ float s_Vo [TILE];
    __shared__ float s_a11[TILE];
    __shared__ float s_a22[TILE];
    __shared__ float s_pxx[TILE];
    __shared__ float s_pxy[TILE];
    __shared__ float s_pex[TILE];
    __shared__ float s_pey[TILE];
    __shared__ float s_Jm [TILE];

    const int bx = blockIdx.x, by = blockIdx.y;
    const int lx = threadIdx.x, ly = threadIdx.y;
    const int tid = ly * TXg + lx;

    // ---- cooperative fill of extended tile ----
    for (int s = tid; s < TILE; s += NTHR) {
        int ly2 = s / EXT_W;
        int lx2 = s - ly2 * EXT_W;
        int ie = bx * TXg + lx2;
        int je = by * OUT_H + ly2;

        F3 en = ext_val(ouv,     ny, je, ie);
        F3 eo = ext_val(ouv_old, ny, je, ie);
        int e = je * EX + ie;
        if (e == PRESS_E) en.z = 0.0f;

        float dxx = ebm[5*e + 0];
        float dxy = ebm[5*e + 1];
        float dex = ebm[5*e + 2];
        float dey = ebm[5*e + 3];
        float Jm  = ebm[5*e + 4];
        float rJ  = __fdividef(1.0f, Jm);

        s_eu [s] = en.x;  s_ev [s] = en.y;  s_ep [s] = en.z;
        s_eou[s] = eo.x;  s_eov[s] = eo.y;
        s_U  [s] = (en.x*dxx + en.y*dxy) * rJ;
        s_V  [s] = (en.x*dex + en.y*dey) * rJ;
        s_Uo [s] = (eo.x*dxx + eo.y*dxy) * rJ;
        s_Vo [s] = (eo.x*dex + eo.y*dey) * rJ;
        s_a11[s] = (dxx*dxx + dxy*dxy) * rJ;
        s_a22[s] = (dex*dex + dey*dey) * rJ;
        float pq = en.z * rJ;
        s_pxx[s] = pq * dxx;
        s_pxy[s] = pq * dxy;
        s_pex[s] = pq * dex;
        s_pey[s] = pq * dey;
        s_Jm [s] = Jm;
    }
    __syncthreads();

    // ---- per-thread column of KY outputs, rolling 3-row window ----
    const float dt    = __ldg(dtg);
    const float uc    = __ldg(theta + 0);
    const float cc    = __ldg(theta + 1);
    const float convc = __ldg(theta + 2);
    const float pc    = __ldg(theta + 3);
    const float dc    = __ldg(theta + 4);
    const float relax = __ldg(relp);

    const int C = lx + 1;
    const int row0 = KY * ly;        // first window row (= ext tile row of y-1 halo)

#define LOAD_ROW(W, RR) do {                                    \
        int b_ = (RR) * EXT_W + C;                              \
        (W).eu[0] = s_eu[b_-1]; (W).eu[1] = s_eu[b_]; (W).eu[2] = s_eu[b_+1]; \
        (W).ev[0] = s_ev[b_-1]; (W).ev[1] = s_ev[b_]; (W).ev[2] = s_ev[b_+1]; \
        (W).ep[0] = s_ep[b_-1]; (W).ep[1] = s_ep[b_]; (W).ep[2] = s_ep[b_+1]; \
        (W).eou = s_eou[b_]; (W).eov = s_eov[b_];               \
        (W).V = s_V[b_]; (W).Vo = s_Vo[b_]; (W).a22 = s_a22[b_]; \
        (W).pex = s_pex[b_]; (W).pey = s_pey[b_];               \
    } while (0)

    Row w[3];
    LOAD_ROW(w[0], row0);
    LOAD_ROW(w[1], row0 + 1);

    const int io = bx * TXg + lx;
    int jo = by * OUT_H + KY * ly;

    #pragma unroll
    for (int ky = 0; ky < KY; ky++) {
        Row& M = w[ky % 3];          // row y-1
        Row& Cc = w[(ky + 1) % 3];   // row y
        Row& P = w[(ky + 2) % 3];    // row y+1
        LOAD_ROW(P, row0 + ky + 2);

        const int b = (row0 + ky + 1) * EXT_W + C;  // center

        // row-only taps
        float Ul = s_U[b-1],  Uc = s_U[b],  Ur = s_U[b+1];
        float Uol = s_Uo[b-1], Uoc = s_Uo[b], Uor = s_Uo[b+1];
        float a11l = s_a11[b-1], a11c = s_a11[b], a11r = s_a11[b+1];
        float pxxl = s_pxx[b-1], pxxr = s_pxx[b+1];
        float pxyl = s_pxy[b-1], pxyr = s_pxy[b+1];
        float eoul = s_eou[b-1], eour = s_eou[b+1];
        float eovl = s_eov[b-1], eovr = s_eov[b+1];
        float Jm = s_Jm[b];

        // window taps
        float euc = Cc.eu[1], eul = Cc.eu[0], eur = Cc.eu[2];
        float eud = M.eu[1],  euu = P.eu[1];
        float eudl = M.eu[0], eudr = M.eu[2], euul = P.eu[0], euur = P.eu[2];
        float evc = Cc.ev[1], evl = Cc.ev[0], evr = Cc.ev[2];
        float evd = M.ev[1],  evu = P.ev[1];
        float evdl = M.ev[0], evdr = M.ev[2], evul = P.ev[0], evur = P.ev[2];
        float epc = Cc.ep[1], epl = Cc.ep[0], epr = Cc.ep[2];
        float epd = M.ep[1],  epu = P.ep[1];
        float epdl = M.ep[0], epdr = M.ep[2], epul = P.ep[0], epur = P.ep[2];

        float Vd = M.V, Vc = Cc.V, Vu = P.V;
        float Vod = M.Vo, Voc = Cc.Vo, Vou = P.Vo;
        float a22d = M.a22, a22c = Cc.a22, a22u = P.a22;
        float eouc = Cc.eou, eoud = M.eou, eouu = P.eou;
        float eovc = Cc.eov, eovd = M.eov, eovu = P.eov;

        // continuity
        float loss = 0.5f * ((Ur - Ul) + (Vu - Vd)) * cc;

        // convection (new)
        float cnu = 0.25f * ((euc + eur) * (Uc + Ur) - (eul + euc) * (Ul + Uc))
                  + 0.25f * ((euc + euu) * (Vc + Vu) - (eud + euc) * (Vd + Vc));
        float cnv = 0.25f * ((evc + evr) * (Uc + Ur) - (evl + evc) * (Ul + Uc))
                  + 0.25f * ((evc + evu) * (Vc + Vu) - (evd + evc) * (Vd + Vc));

        // convection (old)
        float cou = 0.25f * ((eouc + eour) * (Uoc + Uor) - (eoul + eouc) * (Uol + Uoc))
                  + 0.25f * ((eouc + eouu) * (Voc + Vou) - (eoud + eouc) * (Vod + Voc));
        float cov = 0.25f * ((eovc + eovr) * (Uoc + Uor) - (eovl + eovc) * (Uol + Uoc))
                  + 0.25f * ((eovc + eovu) * (Voc + Vou) - (eovd + eovc) * (Vod + Voc));

        float convu = relax * cou + (1.0f - relax) * cnu;
        float convv = relax * cov + (1.0f - relax) * cnv;

        // diffusion (new)
        float difu = 0.5f * ((a11c + a11r) * (eur - euc) - (a11l + a11c) * (euc - eul))
                   + 0.5f * ((a22c + a22u) * (euu - euc) - (a22d + a22c) * (euc - eud));
        float difv = 0.5f * ((a11c + a11r) * (evr - evc) - (a11l + a11c) * (evc - evl))
                   + 0.5f * ((a22c + a22u) * (evu - evc) - (a22d + a22c) * (evc - evd));

        // pressure gradient
        float gPx = 0.5f * (pxxr - pxxl) + 0.5f * (P.pex - M.pex);
        float gPy = 0.5f * (P.pey - M.pey) + 0.5f * (pxyr - pxyl);

        // unsteady (interior ext == raw uvp; J_o == Jm)
        float inv = __fdividef(1.0f, dt * Jm);
        float unu = (euc - eouc) * inv;
        float unv = (evc - eovc) * inv;

        float momu = uc * unu + convc * convu + pc * gPx - dc * difu;
        float momv = uc * unv + convc * convv + pc * gPy - dc * difv;

        // uvp_to_vis: (1-2-1)^2 / 16 binomial
        const float sw = 1.0f / 16.0f;
        float visu = sw * (4.0f*euc + 2.0f*(eul + eur + eud + euu) + (eudl + eudr + euul + euur));
        float visv = sw * (4.0f*evc + 2.0f*(evl + evr + evd + evu) + (evdl + evdr + evul + evur));
        float visp = sw * (4.0f*epc + 2.0f*(epl + epr + epd + epu) + (epdl + epdr + epul + epur));

        const int o = jo * NXg + io;
        out[o]          = loss;
        out[NN + o]     = momu;
        out[2*NN + o]   = momv;
        out[3*NN + 3*o]     = visu;
        out[3*NN + 3*o + 1] = visv;
        out[3*NN + 3*o + 2] = visp;
        jo++;
    }
#undef LOAD_ROW
}

extern "C" void kernel_launch(void* const* d_in, const int* in_sizes, int n_in,
                              void* d_out, int out_size) {
    const float* ouv     = (const float*)d_in[0];
    const float* ouv_old = (const float*)d_in[1];
    const float* ny      = (const float*)d_in[2];
    // d_in[3] (obm) unused: obm == ebm[interior]
    const float* ebm     = (const float*)d_in[4];
    const float* dtg     = (const float*)d_in[5];
    const float* theta   = (const float*)d_in[6];
    const float* relp    = (const float*)d_in[7];
    float* out = (float*)d_out;

    dim3 block(TXg, TYg);
    dim3 grid(NXg / TXg, NYg / OUT_H);
    fused_kernel<<<grid, block>>>(ouv, ouv_old, ny, ebm, dtg, theta, relp, out);
}

// round 4
// speedup vs baseline: 1.4576x; 1.4576x over previous
#include <cuda_runtime.h>

// FD_discretizer: fused single-kernel, KY=2 coarsened, direct-smem stencil.
// 1024x1024 grid, extended 1026x1026. Index arrays closed-form in (i,j).
// Identities: obm == ebm[interior]; interior ext == raw uvp.

#define NXg 1024
#define NYg 1024
#define EX  1026
#define EY  1026
#define NN  (NXg*NYg)

#define PRESS_E (513*EX + 513)

#define TXg 32
#define TYg 8
#define KY  2
#define NTHR (TXg*TYg)           // 256
#define OUT_H (TYg*KY)           // 16
#define EXT_W (TXg + 2)          // 34
#define EXT_H (OUT_H + 2)        // 18
#define TILE  (EXT_W * EXT_H)    // 612

__device__ __forceinline__ int clampi(int x, int lo, int hi) {
    return x < lo ? lo : (x > hi ? hi : x);
}
__device__ __forceinline__ int eidx(int je, int ie) {
    return clampi(je - 1, 0, NYg - 1) * NXg + clampi(ie - 1, 0, NXg - 1);
}

struct F3 { float x, y, z; };

__device__ __forceinline__ void dummy_uv(const float* __restrict__ uvp,
                                         const float* __restrict__ ny,
                                         int m, float& du, float& dv) {
    int io = m % NXg;
    int jo = m / NXg;
    bool bc = (io == 0) || (io != NXg - 1 && (jo == 0 || jo == NYg - 1));
    if (bc) { du = ny[3*m]; dv = ny[3*m+1]; }
    else    { du = uvp[3*m]; dv = uvp[3*m+1]; }
}
__device__ __forceinline__ float dummy_p(const float* __restrict__ uvp, int m) {
    int io = m % NXg;
    return (io == NXg - 1) ? 0.0f : uvp[3*m+2];
}

__device__ __forceinline__ F3 ext_val(const float* __restrict__ uvp,
                                      const float* __restrict__ ny,
                                      int je, int ie) {
    F3 r;
    bool jin = (je >= 1) & (je <= EY - 2);
    if (ie == 0 && jin) {               // left ghost: INFLOW -> pmask
        int m1 = eidx(je, 1), m2 = eidx(je, 2);
        float du, dv; dummy_uv(uvp, ny, m1, du, dv);
        r.x = 2.0f*du - uvp[3*m2];
        r.y = 2.0f*dv - uvp[3*m2+1];
        r.z = uvp[3*m2+2];
    } else if (ie == EX - 1 && jin) {   // right ghost: OUTFLOW -> uvmask
        int m1 = eidx(je, EX - 2), m2 = eidx(je, EX - 3);
        float dp = dummy_p(uvp, m1);
        r.x = uvp[3*m2];
        r.y = uvp[3*m2+1];
        r.z = 2.0f*dp - uvp[3*m2+2];
    } else if (je == 0 && ie >= 1 && ie <= EX - 2) {   // bottom ghost: WALL
        int m1 = eidx(1, ie), m2 = eidx(2, ie);
        float du, dv; dummy_uv(uvp, ny, m1, du, dv);
        r.x = 2.0f*du - uvp[3*m2];
        r.y = 2.0f*dv - uvp[3*m2+1];
        r.z = uvp[3*m2+2];
    } else if (je == EY - 1 && ie >= 1 && ie <= EX - 2) {  // top ghost: WALL
        int m1 = eidx(EY - 2, ie), m2 = eidx(EY - 3, ie);
        float du, dv; dummy_uv(uvp, ny, m1, du, dv);
        r.x = 2.0f*du - uvp[3*m2];
        r.y = 2.0f*dv - uvp[3*m2+1];
        r.z = uvp[3*m2+2];
    } else {
        int m = eidx(je, ie);
        r.x = uvp[3*m]; r.y = uvp[3*m+1]; r.z = uvp[3*m+2];
    }
    return r;
}

__global__ void __launch_bounds__(NTHR, 5)
fused_kernel(const float* __restrict__ ouv,
             const float* __restrict__ ouv_old,
             const float* __restrict__ ny,
             const float* __restrict__ ebm,
             const float* __restrict__ dtg,
             const float* __restrict__ theta,
             const float* __restrict__ relp,
             float* __restrict__ out) {
    __shared__ float s_eu [TILE];
    __shared__ float s_ev [TILE];
    __shared__ float s_ep [TILE];
    __shared__ float s_eou[TILE];
    __shared__ float s_eov[TILE];
    __shared__ float s_U  [TILE];
    __shared__ float s_V  [TILE];
    __shared__ float s_Uo [TILE];
    __shared__ float s_Vo [TILE];
    __shared__ float s_a11[TILE];
    __shared__ float s_a22[TILE];
    __shared__ float s_pxx[TILE];
    __shared__ float s_pxy[TILE];
    __shared__ float s_pex[TILE];
    __shared__ float s_pey[TILE];
    __shared__ float s_rJ [TILE];

    const int bx = blockIdx.x, by = blockIdx.y;
    const int lx = threadIdx.x, ly = threadIdx.y;
    const int tid = ly * TXg + lx;

    // ---- cooperative fill of extended tile ----
    for (int s = tid; s < TILE; s += NTHR) {
        int ly2 = s / EXT_W;
        int lx2 = s - ly2 * EXT_W;
        int ie = bx * TXg + lx2;
        int je = by * OUT_H + ly2;

        F3 en = ext_val(ouv,     ny, je, ie);
        F3 eo = ext_val(ouv_old, ny, je, ie);
        int e = je * EX + ie;
        if (e == PRESS_E) en.z = 0.0f;

        float dxx = ebm[5*e + 0];
        float dxy = ebm[5*e + 1];
        float dex = ebm[5*e + 2];
        float dey = ebm[5*e + 3];
        float Jm  = ebm[5*e + 4];
        float rJ  = __fdividef(1.0f, Jm);

        s_eu [s] = en.x;  s_ev [s] = en.y;  s_ep [s] = en.z;
        s_eou[s] = eo.x;  s_eov[s] = eo.y;
        s_U  [s] = (en.x*dxx + en.y*dxy) * rJ;
        s_V  [s] = (en.x*dex + en.y*dey) * rJ;
        s_Uo [s] = (eo.x*dxx + eo.y*dxy) * rJ;
        s_Vo [s] = (eo.x*dex + eo.y*dey) * rJ;
        s_a11[s] = (dxx*dxx + dxy*dxy) * rJ;
        s_a22[s] = (dex*dex + dey*dey) * rJ;
        float pq = en.z * rJ;
        s_pxx[s] = pq * dxx;
        s_pxy[s] = pq * dxy;
        s_pex[s] = pq * dex;
        s_pey[s] = pq * dey;
        s_rJ [s] = rJ;
    }
    __syncthreads();

    // ---- per-thread KY outputs, direct smem reads ----
    const float dt    = __ldg(dtg);
    const float rdt   = __fdividef(1.0f, dt);
    const float uc    = __ldg(theta + 0);
    const float cc    = __ldg(theta + 1);
    const float convc = __ldg(theta + 2);
    const float pc    = __ldg(theta + 3);
    const float dc    = __ldg(theta + 4);
    const float relax = __ldg(relp);

    const int io = bx * TXg + lx;
    const int jo0 = by * OUT_H + KY * ly;

    #pragma unroll
    for (int ky = 0; ky < KY; ky++) {
        const int c = (KY * ly + ky + 1) * EXT_W + (lx + 1);
        const int l = c - 1,      r = c + 1;
        const int d = c - EXT_W,  u = c + EXT_W;

        float Uc = s_U[c], Ul = s_U[l], Ur = s_U[r];
        float Vc = s_V[c], Vd = s_V[d], Vu = s_V[u];
        float loss = 0.5f * ((Ur - Ul) + (Vu - Vd)) * cc;

        float euc = s_eu[c], eul = s_eu[l], eur = s_eu[r], eud = s_eu[d], euu = s_eu[u];
        float evc = s_ev[c], evl = s_ev[l], evr = s_ev[r], evd = s_ev[d], evu = s_ev[u];
        float epc = s_ep[c], epl = s_ep[l], epr = s_ep[r], epd = s_ep[d], epu = s_ep[u];
        float eudl = s_eu[d-1], eudr = s_eu[d+1], euul = s_eu[u-1], euur = s_eu[u+1];
        float evdl = s_ev[d-1], evdr = s_ev[d+1], evul = s_ev[u-1], evur = s_ev[u+1];
        float epdl = s_ep[d-1], epdr = s_ep[d+1], epul = s_ep[u-1], epur = s_ep[u+1];

        // convection (new)
        float cnu = 0.25f * ((euc + eur) * (Uc + Ur) - (eul + euc) * (Ul + Uc))
                  + 0.25f * ((euc + euu) * (Vc + Vu) - (eud + euc) * (Vd + Vc));
        float cnv = 0.25f * ((evc + evr) * (Uc + Ur) - (evl + evc) * (Ul + Uc))
                  + 0.25f * ((evc + evu) * (Vc + Vu) - (evd + evc) * (Vd + Vc));

        // convection (old)
        float Uoc = s_Uo[c], Uol = s_Uo[l], Uor = s_Uo[r];
        float Voc = s_Vo[c], Vod = s_Vo[d], Vou = s_Vo[u];
        float ouc = s_eou[c], oul = s_eou[l], our = s_eou[r], oud = s_eou[d], ouu = s_eou[u];
        float ovc = s_eov[c], ovl = s_eov[l], ovr = s_eov[r], ovd = s_eov[d], ovu = s_eov[u];

        float cou = 0.25f * ((ouc + our) * (Uoc + Uor) - (oul + ouc) * (Uol + Uoc))
                  + 0.25f * ((ouc + ouu) * (Voc + Vou) - (oud + ouc) * (Vod + Voc));
        float cov = 0.25f * ((ovc + ovr) * (Uoc + Uor) - (ovl + ovc) * (Uol + Uoc))
                  + 0.25f * ((ovc + ovu) * (Voc + Vou) - (ovd + ovc) * (Vod + Voc));

        float convu = relax * cou + (1.0f - relax) * cnu;
        float convv = relax * cov + (1.0f - relax) * cnv;

        // diffusion (new)
        float a11c = s_a11[c], a11l = s_a11[l], a11r = s_a11[r];
        float a22c = s_a22[c], a22d = s_a22[d], a22u = s_a22[u];
        float difu = 0.5f * ((a11c + a11r) * (eur - euc) - (a11l + a11c) * (euc - eul))
                   + 0.5f * ((a22c + a22u) * (euu - euc) - (a22d + a22c) * (euc - eud));
        float difv = 0.5f * ((a11c + a11r) * (evr - evc) - (a11l + a11c) * (evc - evl))
                   + 0.5f * ((a22c + a22u) * (evu - evc) - (a22d + a22c) * (evc - evd));

        // pressure gradient
        float gPx = 0.5f * (s_pxx[r] - s_pxx[l]) + 0.5f * (s_pex[u] - s_pex[d]);
        float gPy = 0.5f * (s_pey[u] - s_pey[d]) + 0.5f * (s_pxy[r] - s_pxy[l]);

        // unsteady (interior ext == raw uvp; J_o == Jm)
        float inv = s_rJ[c] * rdt;
        float unu = (euc - ouc) * inv;
        float unv = (evc - ovc) * inv;

        float momu = uc * unu + convc * convu + pc * gPx - dc * difu;
        float momv = uc * unv + convc * convv + pc * gPy - dc * difv;

        // uvp_to_vis: (1-2-1)^2 / 16 binomial
        const float sw = 1.0f / 16.0f;
        float visu = sw * (4.0f*euc + 2.0f*(eul + eur + eud + euu) + (eudl + eudr + euul + euur));
        float visv = sw * (4.0f*evc + 2.0f*(evl + evr + evd + evu) + (evdl + evdr + evul + evur));
        float visp = sw * (4.0f*epc + 2.0f*(epl + epr + epd + epu) + (epdl + epdr + epul + epur));

        const int o = (jo0 + ky) * NXg + io;
        out[o]          = loss;
        out[NN + o]     = momu;
        out[2*NN + o]   = momv;
        out[3*NN + 3*o]     = visu;
        out[3*NN + 3*o + 1] = visv;
        out[3*NN + 3*o + 2] = visp;
    }
}

extern "C" void kernel_launch(void* const* d_in, const int* in_sizes, int n_in,
                              void* d_out, int out_size) {
    const float* ouv     = (const float*)d_in[0];
    const float* ouv_old = (const float*)d_in[1];
    const float* ny      = (const float*)d_in[2];
    // d_in[3] (obm) unused: obm == ebm[interior]
    const float* ebm     = (const float*)d_in[4];
    const float* dtg     = (const float*)d_in[5];
    const float* theta   = (const float*)d_in[6];
    const float* relp    = (const float*)d_in[7];
    float* out = (float*)d_out;

    dim3 block(TXg, TYg);
    dim3 grid(NXg / TXg, NYg / OUT_H);
    fused_kernel<<<grid, block>>>(ouv, ouv_old, ny, ebm, dtg, theta, relp, out);
}